// round 14
// baseline (speedup 1.0000x reference)
#include <cuda_runtime.h>
#include <math.h>

// ---------------------------------------------------------------------------
// CMAF fused block, round 14: fat-tile GEMM core for ALL GEMM stages.
//   CTA 256x128, 8 warps 4(m)x2(n), warp tile 64x64 (128-reg acc),
//   BK=16, 5-stage cp.async pipeline (distance 4), quad-XOR swizzle,
//   LDS.128 fragments. 1 CTA/SM (reg+smem), smem-traffic/MAC -33%.
// ---------------------------------------------------------------------------

#define MAXB 65536
#define BM 256
#define NST 5
#define ASW (BM * 16)          // 4096 words: A stage
#define WSW (128 * 16)         // 2048 words: W stage
#define STW2 (ASW + WSW)       // 6144 words per stage
#define GSMEM (NST * STW2 * 4) // 122880 B

__device__ __align__(16) float g_P [MAXB * 3 * 128];
__device__ __align__(16) float g_q [MAXB * 3 * 128];
__device__ __align__(16) float g_k [MAXB * 6 * 128];
__device__ __align__(16) float g_v [MAXB * 6 * 128];
__device__ __align__(16) float g_o [MAXB * 3 * 128];
__device__ __align__(16) float g_x1[MAXB * 3 * 128];
__device__ __align__(16) float g_h [MAXB * 3 * 256];
__device__ __align__(16) float g_x2[MAXB * 3 * 128];

// tf32-preconverted weights (contiguous: spatial|gf|inw|outw|ffn1|ffn2)
#define WOFF_SPATIAL 0
#define WOFF_GF      163840
#define WOFF_INW     196608
#define WOFF_OUTW    344064
#define WOFF_FFN1    393216
#define WOFF_FFN2    491520
__device__ __align__(16) float g_wtf[589824];

__constant__ int c_kv[3][2] = {{1, 2}, {0, 2}, {0, 1}};

__device__ __forceinline__ unsigned f2tf(float f) {
    unsigned u;
    asm("cvt.rna.tf32.f32 %0, %1;" : "=r"(u) : "f"(f));
    return u;
}
__device__ __forceinline__ float tfr(float f) {
    return __uint_as_float(f2tf(f));
}
__device__ __forceinline__ unsigned fau(float f) { return __float_as_uint(f); }

__device__ __forceinline__ void mma8(float c[4], const unsigned a[4], const unsigned b[2]) {
    asm volatile(
        "mma.sync.aligned.m16n8k8.row.col.f32.tf32.tf32.f32 "
        "{%0,%1,%2,%3}, {%4,%5,%6,%7}, {%8,%9}, {%0,%1,%2,%3};\n"
        : "+f"(c[0]), "+f"(c[1]), "+f"(c[2]), "+f"(c[3])
        : "r"(a[0]), "r"(a[1]), "r"(a[2]), "r"(a[3]), "r"(b[0]), "r"(b[1]));
}

__device__ __forceinline__ void cp16(unsigned smem_dst, const void* gsrc) {
    asm volatile("cp.async.cg.shared.global [%0], [%1], 16;\n"
                 :: "r"(smem_dst), "l"(gsrc));
}
__device__ __forceinline__ void cp_commit() {
    asm volatile("cp.async.commit_group;\n");
}
template <int N>
__device__ __forceinline__ void cp_wait() {
    asm volatile("cp.async.wait_group %0;\n" :: "n"(N));
}

// ---------------------------------------------------------------------------
// Fat epilogue. EPI: 0=bias, 1=bias+gelu, 2=bias+LN+addv, 3=bias+resid+LN
// RND: store tf32-rounded. 8 warps 4(m)x2(n), warp tile 64x64.
// ---------------------------------------------------------------------------
template <int EPI, int RND>
__device__ __forceinline__ void epi_fat(
    float acc[4][8][4],
    const float* __restrict__ bias,
    const float* __restrict__ lng, const float* __restrict__ lnb,
    const float* __restrict__ addv,
    const float* __restrict__ resid, int rstride,
    float* __restrict__ out, int ostride, int m0, int M)
{
    __shared__ float2 pbuf[BM][2];
    const int tid = threadIdx.x, wid = tid >> 5, lane = tid & 31;
    const int wm = (wid & 3) * 64, wn = (wid >> 2) * 64, wq = wid >> 2;
    const int g = lane >> 2, t4 = lane & 3;

    float b2[8][2];
#pragma unroll
    for (int nt = 0; nt < 8; ++nt) {
        const int col = wn + nt * 8 + t4 * 2;
        b2[nt][0] = bias[col]; b2[nt][1] = bias[col + 1];
    }

    if (EPI <= 1) {
#pragma unroll
        for (int mt = 0; mt < 4; ++mt)
#pragma unroll
        for (int hf = 0; hf < 2; ++hf) {
            const int r = m0 + wm + mt * 16 + hf * 8 + g;
            if (r < M) {
                float* orow = out + (long)r * ostride;
#pragma unroll
                for (int nt = 0; nt < 8; ++nt) {
                    const int col = wn + nt * 8 + t4 * 2;
                    float c0 = acc[mt][nt][hf * 2 + 0] + b2[nt][0];
                    float c1 = acc[mt][nt][hf * 2 + 1] + b2[nt][1];
                    if (EPI == 1) {
                        c0 = c0 * 0.5f * (1.0f + erff(c0 * 0.70710678118654752f));
                        c1 = c1 * 0.5f * (1.0f + erff(c1 * 0.70710678118654752f));
                    }
                    if (RND) { c0 = tfr(c0); c1 = tfr(c1); }
                    *(float2*)(orow + col) = make_float2(c0, c1);
                }
            }
        }
        return;
    }

    // LN path
#pragma unroll
    for (int mt = 0; mt < 4; ++mt)
#pragma unroll
    for (int hf = 0; hf < 2; ++hf) {
        const int lr = wm + mt * 16 + hf * 8 + g;
        const int r  = m0 + lr;
        float s = 0.f, s2 = 0.f;
        const float* rrow = (EPI == 3) ? resid + (long)min(r, M - 1) * rstride : (const float*)0;
#pragma unroll
        for (int nt = 0; nt < 8; ++nt) {
            const int col = wn + nt * 8 + t4 * 2;
            float c0 = acc[mt][nt][hf * 2 + 0] + b2[nt][0];
            float c1 = acc[mt][nt][hf * 2 + 1] + b2[nt][1];
            if (EPI == 3) {
                const float2 rv = *(const float2*)(rrow + col);
                c0 += rv.x; c1 += rv.y;
            }
            acc[mt][nt][hf * 2 + 0] = c0; acc[mt][nt][hf * 2 + 1] = c1;
            s += c0 + c1; s2 += c0 * c0 + c1 * c1;
        }
        s  += __shfl_xor_sync(0xffffffffu, s, 1);
        s  += __shfl_xor_sync(0xffffffffu, s, 2);
        s2 += __shfl_xor_sync(0xffffffffu, s2, 1);
        s2 += __shfl_xor_sync(0xffffffffu, s2, 2);
        if (t4 == 0) pbuf[lr][wq] = make_float2(s, s2);
    }
    __syncthreads();
#pragma unroll
    for (int mt = 0; mt < 4; ++mt)
#pragma unroll
    for (int hf = 0; hf < 2; ++hf) {
        const int lr = wm + mt * 16 + hf * 8 + g;
        const int r  = m0 + lr;
        const float2 p0 = pbuf[lr][0], p1 = pbuf[lr][1];
        const float s    = p0.x + p1.x;
        const float s2   = p0.y + p1.y;
        const float mean = s * 0.0078125f;
        const float var  = s2 * 0.0078125f - mean * mean;
        const float rs   = rsqrtf(var + 1e-5f);
        if (r < M) {
            float* orow = out + (long)r * ostride;
#pragma unroll
            for (int nt = 0; nt < 8; ++nt) {
                const int col = wn + nt * 8 + t4 * 2;
                float o0 = (acc[mt][nt][hf * 2 + 0] - mean) * rs * lng[col]     + lnb[col];
                float o1 = (acc[mt][nt][hf * 2 + 1] - mean) * rs * lng[col + 1] + lnb[col + 1];
                if (EPI == 2) { o0 += addv[col]; o1 += addv[col + 1]; }
                if (RND) { o0 = tfr(o0); o1 = tfr(o1); }
                *(float2*)(orow + col) = make_float2(o0, o1);
            }
        }
    }
}

// one 16-k tile: 16 LDS.128 + 64 mma8 per warp, RAW-free nt interleave
__device__ __forceinline__ void tile_fat(
    const float* __restrict__ smem, int stbase,
    int wm, int wn, int g, int tq, float acc[4][8][4])
{
    float4 bf4[8];
    const float* Wb = smem + stbase + ASW;
#pragma unroll
    for (int nt = 0; nt < 8; ++nt)
        bf4[nt] = *(const float4*)&Wb[(wn + nt * 8 + g) * 16 + tq];
    const float* Ab = smem + stbase;
#pragma unroll
    for (int mt = 0; mt < 4; ++mt) {
        const int r = wm + mt * 16 + g;
        const float4 a0 = *(const float4*)&Ab[r * 16 + tq];
        const float4 a1 = *(const float4*)&Ab[(r + 8) * 16 + tq];
        {
            const unsigned aa[4] = {fau(a0.x), fau(a1.x), fau(a0.y), fau(a1.y)};
#pragma unroll
            for (int nt = 0; nt < 8; ++nt) {
                const unsigned bb[2] = {fau(bf4[nt].x), fau(bf4[nt].y)};
                mma8(acc[mt][nt], aa, bb);
            }
        }
        {
            const unsigned aa[4] = {fau(a0.z), fau(a1.z), fau(a0.w), fau(a1.w)};
#pragma unroll
            for (int nt = 0; nt < 8; ++nt) {
                const unsigned bb[2] = {fau(bf4[nt].z), fau(bf4[nt].w)};
                mma8(acc[mt][nt], aa, bb);
            }
        }
    }
}

// ---------------------------------------------------------------------------
// Fat GEMM core. CVTST=1: A staged via LDG+cvt+STS (reg prefetch);
// CVTST=0: A via cp.async (already tf32).
// ---------------------------------------------------------------------------
template <int EPI, int RND, int CVTST>
__device__ __forceinline__ void fat_gemm(
    const float* __restrict__ A, int lda,
    const float* __restrict__ W, int K,
    const float* __restrict__ bias,
    const float* __restrict__ lng, const float* __restrict__ lnb,
    const float* __restrict__ addv,
    const float* __restrict__ resid, int rstride,
    float* __restrict__ out, int ostride,
    int m0, int M)
{
    extern __shared__ float smem[];
    const int tid = threadIdx.x;

    // staging geometry
    const int ar  = tid;                 // A: one row per thread
    const int arw = ar & 3;
    const float* Aptr = A + (long)min(m0 + ar, M - 1) * lda;
    const int wr  = tid >> 1, wh = tid & 1;
    const int wrw = wr & 3;
    const float* Wptr = W + (long)wr * K + wh * 8;

    const unsigned sb = (unsigned)__cvta_generic_to_shared(smem);
    unsigned ast[4], wst[2];
#pragma unroll
    for (int j = 0; j < 4; ++j)
        ast[j] = sb + (ar * 16 + ((j ^ arw) * 4)) * 4;
#pragma unroll
    for (int jj = 0; jj < 2; ++jj)
        wst[jj] = sb + (ASW + wr * 16 + (((wh * 2 + jj) ^ wrw) * 4)) * 4;

    const int wid = tid >> 5, lane = tid & 31;
    const int wm = (wid & 3) * 64, wn = (wid >> 2) * 64;
    const int g = lane >> 2, t4 = lane & 3;
    const int tq = (t4 ^ (g & 3)) * 4;

    float acc[4][8][4] = {};
    const int ntiles = K >> 4;

    float4 rg[4];  // CVTST prefetch regs
    if (CVTST) {
        // tile 0: direct cvt-store
#pragma unroll
        for (int j = 0; j < 4; ++j) {
            const float4 v = *(const float4*)(Aptr + j * 4);
            *(float4*)&smem[ar * 16 + ((j ^ arw) * 4)] =
                make_float4(tfr(v.x), tfr(v.y), tfr(v.z), tfr(v.w));
        }
        // regs for tile 1
#pragma unroll
        for (int j = 0; j < 4; ++j) rg[j] = *(const float4*)(Aptr + 16 + j * 4);
        // W for tiles 0..3
#pragma unroll
        for (int p = 0; p < 4; ++p) {
            cp16(wst[0] + p * STW2 * 4, Wptr + (p << 4));
            cp16(wst[1] + p * STW2 * 4, Wptr + (p << 4) + 4);
            cp_commit();
        }
    } else {
#pragma unroll
        for (int p = 0; p < 4; ++p) {
            const int k0 = p << 4;
#pragma unroll
            for (int j = 0; j < 4; ++j) cp16(ast[j] + p * STW2 * 4, Aptr + k0 + j * 4);
            cp16(wst[0] + p * STW2 * 4, Wptr + k0);
            cp16(wst[1] + p * STW2 * 4, Wptr + k0 + 4);
            cp_commit();
        }
    }

    int cur = 0;
#pragma unroll 1
    for (int t = 0; t < ntiles; ++t) {
        if (t + 4 <= ntiles)      cp_wait<3>();
        else if (t + 3 <= ntiles) cp_wait<2>();
        else if (t + 2 <= ntiles) cp_wait<1>();
        else                      cp_wait<0>();
        __syncthreads();

        if (t + 4 < ntiles) {
            const int buf = cur + 4 >= NST ? cur - 1 : cur + 4;
            const int k0 = (t + 4) << 4;
            if (!CVTST) {
#pragma unroll
                for (int j = 0; j < 4; ++j) cp16(ast[j] + buf * STW2 * 4, Aptr + k0 + j * 4);
            }
            cp16(wst[0] + buf * STW2 * 4, Wptr + k0);
            cp16(wst[1] + buf * STW2 * 4, Wptr + k0 + 4);
            cp_commit();
        }

        if (CVTST) {
            if (t + 1 < ntiles) {
                const int nb = cur + 1 >= NST ? 0 : cur + 1;
#pragma unroll
                for (int j = 0; j < 4; ++j)
                    *(float4*)&smem[nb * STW2 + ar * 16 + ((j ^ arw) * 4)] =
                        make_float4(tfr(rg[j].x), tfr(rg[j].y), tfr(rg[j].z), tfr(rg[j].w));
            }
            if (t + 2 < ntiles) {
                const int k0 = (t + 2) << 4;
#pragma unroll
                for (int j = 0; j < 4; ++j) rg[j] = *(const float4*)(Aptr + k0 + j * 4);
            }
        }

        tile_fat(smem, cur * STW2, wm, wn, g, tq, acc);
        cur = cur + 1 >= NST ? 0 : cur + 1;
    }

    epi_fat<EPI, RND>(acc, bias, lng, lnb, addv, resid, rstride, out, ostride, m0, M);
}

// ---------------- kernels ----------------

// y=0 -> spatial (K=1280), y=1,2 -> gf stream y-1
__global__ __launch_bounds__(256, 1) void k_f_proj(
    const float* __restrict__ Xs, const float* __restrict__ Xg,
    const float* __restrict__ Xf,
    const float* __restrict__ pb, const float* __restrict__ lng,
    const float* __restrict__ lnb, const float* __restrict__ mod, int M)
{
    const int y = blockIdx.y;
    if (y == 0) {
        fat_gemm<2, 1, 1>(Xs, 1280, g_wtf + WOFF_SPATIAL, 1280, pb, lng, lnb, mod,
                          nullptr, 0, g_P, 384, blockIdx.x * BM, M);
    } else {
        const int s = y - 1, n = y;
        fat_gemm<2, 1, 1>(s ? Xf : Xg, 128, g_wtf + WOFF_GF + s * 128 * 128, 128,
                          pb + n * 128, lng + n * 128, lnb + n * 128, mod + n * 128,
                          nullptr, 0, g_P + n * 128, 384, blockIdx.x * BM, M);
    }
}

// y = 0..14: one (stream, q/k/v) job each; A (P) is L2-hot across jobs
__global__ __launch_bounds__(256, 1) void k_f_qkv(
    const float* __restrict__ Bi, int M)
{
    const int y = blockIdx.y;
    const int n = y / 5, t = y % 5;
    int src, wpart, ostride;
    float* outp;
    if (t == 0)      { src = n;             wpart = 0; outp = g_q + n * 128;               ostride = 384; }
    else if (t <= 2) { const int s = t - 1; src = c_kv[n][s]; wpart = 1; outp = g_k + (n * 2 + s) * 128; ostride = 768; }
    else             { const int s = t - 3; src = c_kv[n][s]; wpart = 2; outp = g_v + (n * 2 + s) * 128; ostride = 768; }
    fat_gemm<0, 0, 0>(g_P + src * 128, 384,
                      g_wtf + WOFF_INW + n * 49152 + wpart * 16384, 128,
                      Bi + n * 384 + wpart * 128,
                      nullptr, nullptr, nullptr, nullptr, 0,
                      outp, ostride, blockIdx.x * BM, M);
}

__global__ __launch_bounds__(256, 1) void k_f_outproj(
    const float* __restrict__ bo,
    const float* __restrict__ ag, const float* __restrict__ ab, int M)
{
    const int n = blockIdx.y;
    fat_gemm<3, 1, 0>(g_o + n * 128, 384, g_wtf + WOFF_OUTW + n * 16384, 128,
                      bo + n * 128, ag + n * 128, ab + n * 128, nullptr,
                      g_P + n * 128, 384, g_x1 + n * 128, 384, blockIdx.x * BM, M);
}

// y = 0..5: (stream n = y>>1, half tl = y&1)
__global__ __launch_bounds__(256, 1) void k_f_ffn1(
    const float* __restrict__ B1, int M)
{
    const int y = blockIdx.y;
    const int n = y >> 1, tl = y & 1;
    fat_gemm<1, 1, 0>(g_x1 + n * 128, 384,
                      g_wtf + WOFF_FFN1 + n * 32768 + tl * 16384, 128,
                      B1 + n * 256 + tl * 128,
                      nullptr, nullptr, nullptr, nullptr, 0,
                      g_h + n * 256 + tl * 128, 768, blockIdx.x * BM, M);
}

__global__ __launch_bounds__(256, 1) void k_f_ffn2(
    const float* __restrict__ B2,
    const float* __restrict__ fg, const float* __restrict__ fb, int M)
{
    const int n = blockIdx.y;
    fat_gemm<3, 0, 0>(g_h + n * 256, 768, g_wtf + WOFF_FFN2 + n * 32768, 256,
                      B2 + n * 128, fg + n * 128, fb + n * 128, nullptr,
                      g_x1 + n * 128, 384, g_x2 + n * 128, 384, blockIdx.x * BM, M);
}

// ---------------- weight tf32 pre-convert (single launch) ----------------
__global__ __launch_bounds__(256) void k_cvt_all(
    const float* __restrict__ s0, const float* __restrict__ s1,
    const float* __restrict__ s2, const float* __restrict__ s3,
    const float* __restrict__ s4, const float* __restrict__ s5)
{
    const int i = blockIdx.x * 256 + threadIdx.x;
    if (i >= 147456) return;
    const float* src; int base;
    if      (i <  40960) { src = s0; base = 0;      }
    else if (i <  49152) { src = s1; base = 40960;  }
    else if (i <  86016) { src = s2; base = 49152;  }
    else if (i <  98304) { src = s3; base = 86016;  }
    else if (i < 122880) { src = s4; base = 98304;  }
    else                 { src = s5; base = 122880; }
    const float4 v = ((const float4*)src)[i - base];
    float4 o;
    o.x = tfr(v.x); o.y = tfr(v.y); o.z = tfr(v.z); o.w = tfr(v.w);
    ((float4*)g_wtf)[i] = o;
}

// ---------------- Attention + gate ----------------

__global__ __launch_bounds__(256) void k_attn(int M)
{
    const int rid = blockIdx.x * 8 + (threadIdx.x >> 5);
    if (rid >= M * 3) return;
    const int lane = threadIdx.x & 31;
    const int d4 = lane * 4;
    const long qb = (long)rid * 128;
    const long kb = (long)rid * 256;

    const float4 q4  = *(const float4*)(g_q + qb + d4);
    const float4 k04 = *(const float4*)(g_k + kb + d4);
    const float4 k14 = *(const float4*)(g_k + kb + 128 + d4);
    const float4 v04 = *(const float4*)(g_v + kb + d4);
    const float4 v14 = *(const float4*)(g_v + kb + 128 + d4);

    float s0 = q4.x * k04.x + q4.y * k04.y + q4.z * k04.z + q4.w * k04.w;
    float s1 = q4.x * k14.x + q4.y * k14.y + q4.z * k14.z + q4.w * k14.w;
#pragma unroll
    for (int o = 4; o; o >>= 1) {
        s0 += __shfl_xor_sync(0xffffffffu, s0, o);
        s1 += __shfl_xor_sync(0xffffffffu, s1, o);
    }
    const float scale = 0.17677669529663687f;
    s0 *= scale; s1 *= scale;
    const float mx = fmaxf(s0, s1);
    const float e0 = expf(s0 - mx), e1 = expf(s1 - mx);
    const float inv = 1.0f / (e0 + e1);
    const float w0 = e0 * inv, w1 = e1 * inv;

    float4 o4;   // tf32-rounded: feeds outproj GEMM as A
    o4.x = tfr(w0 * v04.x + w1 * v14.x);
    o4.y = tfr(w0 * v04.y + w1 * v14.y);
    o4.z = tfr(w0 * v04.z + w1 * v14.z);
    o4.w = tfr(w0 * v04.w + w1 * v14.w);
    *(float4*)(g_o + qb + d4) = o4;
}

__global__ __launch_bounds__(256) void k_gate(
    const float* __restrict__ gw, const float* __restrict__ gb,
    float* __restrict__ out, int M)
{
    const int b = blockIdx.x * 8 + (threadIdx.x >> 5);
    if (b >= M) return;
    const int lane = threadIdx.x & 31;
    const float* xr = g_x2 + (long)b * 384;
    float l0 = 0.f, l1 = 0.f, l2 = 0.f;
#pragma unroll
    for (int j = 0; j < 12; ++j) {
        const int idx = lane + 32 * j;
        const float x = xr[idx];
        l0 += x * gw[idx];
        l1 += x * gw[384 + idx];
        l2 += x * gw[768 + idx];
    }
#pragma unroll
    for (int o = 16; o; o >>= 1) {
        l0 += __shfl_xor_sync(0xffffffffu, l0, o);
        l1 += __shfl_xor_sync(0xffffffffu, l1, o);
        l2 += __shfl_xor_sync(0xffffffffu, l2, o);
    }
    l0 += gb[0]; l1 += gb[1]; l2 += gb[2];
    const float mx = fmaxf(l0, fmaxf(l1, l2));
    const float e0 = expf(l0 - mx), e1 = expf(l1 - mx), e2 = expf(l2 - mx);
    const float inv = 1.0f / (e0 + e1 + e2);
    const float w0 = e0 * inv, w1 = e1 * inv, w2 = e2 * inv;
#pragma unroll
    for (int j = 0; j < 4; ++j) {
        const int d = lane + 32 * j;
        out[(long)b * 128 + d] = w0 * xr[d] + w1 * xr[128 + d] + w2 * xr[256 + d];
    }
}

// ---------------------------------------------------------------------------

extern "C" void kernel_launch(void* const* d_in, const int* in_sizes, int n_in,
                              void* d_out, int out_size)
{
    const float* x_spatial   = (const float*)d_in[0];
    const float* x_gradient  = (const float*)d_in[1];
    const float* x_frequency = (const float*)d_in[2];
    const float* w_spatial   = (const float*)d_in[3];
    const float* w_gf        = (const float*)d_in[4];
    const float* proj_b      = (const float*)d_in[5];
    const float* proj_ln_g   = (const float*)d_in[6];
    const float* proj_ln_b   = (const float*)d_in[7];
    const float* mod_emb     = (const float*)d_in[8];
    const float* in_w        = (const float*)d_in[9];
    const float* in_b        = (const float*)d_in[10];
    const float* out_w       = (const float*)d_in[11];
    const float* out_b       = (const float*)d_in[12];
    const float* attn_g      = (const float*)d_in[13];
    const float* attn_b      = (const float*)d_in[14];
    const float* w1          = (const float*)d_in[15];
    const float* b1          = (const float*)d_in[16];
    const float* w2          = (const float*)d_in[17];
    const float* b2          = (const float*)d_in[18];
    const float* ffn_g       = (const float*)d_in[19];
    const float* ffn_b       = (const float*)d_in[20];
    const float* gate_w      = (const float*)d_in[21];
    const float* gate_b      = (const float*)d_in[22];
    float* out = (float*)d_out;

    static int smem_set = 0;
    if (!smem_set) {
        cudaFuncSetAttribute(k_f_proj,    cudaFuncAttributeMaxDynamicSharedMemorySize, GSMEM);
        cudaFuncSetAttribute(k_f_qkv,     cudaFuncAttributeMaxDynamicSharedMemorySize, GSMEM);
        cudaFuncSetAttribute(k_f_outproj, cudaFuncAttributeMaxDynamicSharedMemorySize, GSMEM);
        cudaFuncSetAttribute(k_f_ffn1,    cudaFuncAttributeMaxDynamicSharedMemorySize, GSMEM);
        cudaFuncSetAttribute(k_f_ffn2,    cudaFuncAttributeMaxDynamicSharedMemorySize, GSMEM);
        smem_set = 1;
    }

    int B = in_sizes[0] / 1280;
    if (B > MAXB) B = MAXB;
    const int gm = (B + BM - 1) / BM;
    const int R  = B * 3;

    k_cvt_all<<<(147456 + 255) / 256, 256>>>(w_spatial, w_gf, in_w, out_w, w1, w2);

    k_f_proj<<<dim3(gm, 3), 256, GSMEM>>>(x_spatial, x_gradient, x_frequency,
                                          proj_b, proj_ln_g, proj_ln_b, mod_emb, B);
    k_f_qkv<<<dim3(gm, 15), 256, GSMEM>>>(in_b, B);
    k_attn<<<(R + 7) / 8, 256>>>(B);
    k_f_outproj<<<dim3(gm, 3), 256, GSMEM>>>(out_b, attn_g, attn_b, B);
    k_f_ffn1<<<dim3(gm, 6), 256, GSMEM>>>(b1, B);
    k_f_ffn2<<<dim3(gm, 3), 256, GSMEM>>>(b2, ffn_g, ffn_b, B);
    k_gate<<<(B + 7) / 8, 256>>>(gate_w, gate_b, out, B);
}

// round 15
// speedup vs baseline: 1.2140x; 1.2140x over previous
#include <cuda_runtime.h>
#include <math.h>

// ---------------------------------------------------------------------------
// CMAF fused block, round 15 = round 13 (best: 1042.5us) +
//   RAW-spaced MMA issue in tile_mma: same-accumulator reuse distance 1 -> 4
//   instructions (bit-identical math; asm volatile previously forced
//   back-to-back dependent HMMA on the same accumulator).
// ---------------------------------------------------------------------------

#define MAXB 65536
#define NST 4
#define STW 2048                         // words per stage (128 rows x 16)
#define GSMEM (2 * NST * STW * 4)        // 65536 B (generic path)

#define AFP2 144                         // resident-A row stride (=16 mod 32)
#define QW2 (128 * AFP2)                 // words
#define QSMEM ((QW2 + NST * STW) * 4)    // 106496 B (resident path)

__device__ __align__(16) float g_P [MAXB * 3 * 128];
__device__ __align__(16) float g_q [MAXB * 3 * 128];
__device__ __align__(16) float g_k [MAXB * 6 * 128];
__device__ __align__(16) float g_v [MAXB * 6 * 128];
__device__ __align__(16) float g_o [MAXB * 3 * 128];
__device__ __align__(16) float g_x1[MAXB * 3 * 128];
__device__ __align__(16) float g_h [MAXB * 3 * 256];
__device__ __align__(16) float g_x2[MAXB * 3 * 128];

// tf32-preconverted weights (contiguous: spatial|gf|inw|outw|ffn1|ffn2)
#define WOFF_SPATIAL 0
#define WOFF_GF      163840
#define WOFF_INW     196608
#define WOFF_OUTW    344064
#define WOFF_FFN1    393216
#define WOFF_FFN2    491520
__device__ __align__(16) float g_wtf[589824];

// QKV jobs per source stream s: {w_off (within in_w), b_off, buf_id, out_off}
__constant__ int qkv_jobs[3][5][4] = {
    { {     0,    0, 0,   0}, { 65536,  512, 1, 256}, { 81920,  640, 2, 256},
      {114688,  896, 1, 512}, {131072, 1024, 2, 512} },
    { { 49152,  384, 0, 128}, { 16384,  128, 1,   0}, { 32768,  256, 2,   0},
      {114688,  896, 1, 640}, {131072, 1024, 2, 640} },
    { { 98304,  768, 0, 256}, { 16384,  128, 1, 128}, { 32768,  256, 2, 128},
      { 65536,  512, 1, 384}, { 81920,  640, 2, 384} },
};

__device__ __forceinline__ unsigned f2tf(float f) {
    unsigned u;
    asm("cvt.rna.tf32.f32 %0, %1;" : "=r"(u) : "f"(f));
    return u;
}
__device__ __forceinline__ float tfr(float f) {
    return __uint_as_float(f2tf(f));
}
__device__ __forceinline__ unsigned fau(float f) { return __float_as_uint(f); }

__device__ __forceinline__ void mma8(float c[4], const unsigned a[4], const unsigned b[2]) {
    asm volatile(
        "mma.sync.aligned.m16n8k8.row.col.f32.tf32.tf32.f32 "
        "{%0,%1,%2,%3}, {%4,%5,%6,%7}, {%8,%9}, {%0,%1,%2,%3};\n"
        : "+f"(c[0]), "+f"(c[1]), "+f"(c[2]), "+f"(c[3])
        : "r"(a[0]), "r"(a[1]), "r"(a[2]), "r"(a[3]), "r"(b[0]), "r"(b[1]));
}

__device__ __forceinline__ void cp16(unsigned smem_dst, const void* gsrc) {
    asm volatile("cp.async.cg.shared.global [%0], [%1], 16;\n"
                 :: "r"(smem_dst), "l"(gsrc));
}
__device__ __forceinline__ void cp_commit() {
    asm volatile("cp.async.commit_group;\n");
}
template <int N>
__device__ __forceinline__ void cp_wait() {
    asm volatile("cp.async.wait_group %0;\n" :: "n"(N));
}

// ---------------------------------------------------------------------------
// Epilogue. EPI: 0=bias, 1=bias+gelu, 2=bias+LN+addv, 3=bias+resid+LN
// RND: store tf32-rounded.
// ---------------------------------------------------------------------------
template <int EPI, int RND>
__device__ __forceinline__ void epi_store(
    float acc[4][4][4],
    const float* __restrict__ bias,
    const float* __restrict__ lng, const float* __restrict__ lnb,
    const float* __restrict__ addv,
    const float* __restrict__ resid, int rstride,
    float* __restrict__ out, int ostride, int m0, int M)
{
    __shared__ float2 pbuf[128][4];
    const int tid = threadIdx.x, wid = tid >> 5, lane = tid & 31;
    const int wm = (wid & 1) * 64, wn = (wid >> 1) * 32, wq = wid >> 1;
    const int g = lane >> 2, t4 = lane & 3;

    float b2[4][2];
#pragma unroll
    for (int nt = 0; nt < 4; ++nt) {
        const int col = wn + nt * 8 + t4 * 2;
        b2[nt][0] = bias[col]; b2[nt][1] = bias[col + 1];
    }

    if (EPI <= 1) {
#pragma unroll
        for (int mt = 0; mt < 4; ++mt)
#pragma unroll
        for (int hf = 0; hf < 2; ++hf) {
            const int r = m0 + wm + mt * 16 + hf * 8 + g;
            if (r < M) {
                float* orow = out + (long)r * ostride;
#pragma unroll
                for (int nt = 0; nt < 4; ++nt) {
                    const int col = wn + nt * 8 + t4 * 2;
                    float c0 = acc[mt][nt][hf * 2 + 0] + b2[nt][0];
                    float c1 = acc[mt][nt][hf * 2 + 1] + b2[nt][1];
                    if (EPI == 1) {
                        c0 = c0 * 0.5f * (1.0f + erff(c0 * 0.70710678118654752f));
                        c1 = c1 * 0.5f * (1.0f + erff(c1 * 0.70710678118654752f));
                    }
                    if (RND) { c0 = tfr(c0); c1 = tfr(c1); }
                    *(float2*)(orow + col) = make_float2(c0, c1);
                }
            }
        }
        return;
    }

    // LN path
#pragma unroll
    for (int mt = 0; mt < 4; ++mt)
#pragma unroll
    for (int hf = 0; hf < 2; ++hf) {
        const int lr = wm + mt * 16 + hf * 8 + g;
        const int r  = m0 + lr;
        float s = 0.f, s2 = 0.f;
        const float* rrow = (EPI == 3) ? resid + (long)min(r, M - 1) * rstride : (const float*)0;
#pragma unroll
        for (int nt = 0; nt < 4; ++nt) {
            const int col = wn + nt * 8 + t4 * 2;
            float c0 = acc[mt][nt][hf * 2 + 0] + b2[nt][0];
            float c1 = acc[mt][nt][hf * 2 + 1] + b2[nt][1];
            if (EPI == 3) {
                const float2 rv = *(const float2*)(rrow + col);
                c0 += rv.x; c1 += rv.y;
            }
            acc[mt][nt][hf * 2 + 0] = c0; acc[mt][nt][hf * 2 + 1] = c1;
            s += c0 + c1; s2 += c0 * c0 + c1 * c1;
        }
        s  += __shfl_xor_sync(0xffffffffu, s, 1);
        s  += __shfl_xor_sync(0xffffffffu, s, 2);
        s2 += __shfl_xor_sync(0xffffffffu, s2, 1);
        s2 += __shfl_xor_sync(0xffffffffu, s2, 2);
        if (t4 == 0) pbuf[lr][wq] = make_float2(s, s2);
    }
    __syncthreads();
#pragma unroll
    for (int mt = 0; mt < 4; ++mt)
#pragma unroll
    for (int hf = 0; hf < 2; ++hf) {
        const int lr = wm + mt * 16 + hf * 8 + g;
        const int r  = m0 + lr;
        const float2 p0 = pbuf[lr][0], p1 = pbuf[lr][1], p2 = pbuf[lr][2], p3 = pbuf[lr][3];
        const float s    = p0.x + p1.x + p2.x + p3.x;
        const float s2   = p0.y + p1.y + p2.y + p3.y;
        const float mean = s * 0.0078125f;
        const float var  = s2 * 0.0078125f - mean * mean;
        const float rs   = rsqrtf(var + 1e-5f);
        if (r < M) {
            float* orow = out + (long)r * ostride;
#pragma unroll
            for (int nt = 0; nt < 4; ++nt) {
                const int col = wn + nt * 8 + t4 * 2;
                float o0 = (acc[mt][nt][hf * 2 + 0] - mean) * rs * lng[col]     + lnb[col];
                float o1 = (acc[mt][nt][hf * 2 + 1] - mean) * rs * lng[col + 1] + lnb[col + 1];
                if (EPI == 2) { o0 += addv[col]; o1 += addv[col + 1]; }
                if (RND) { o0 = tfr(o0); o1 = tfr(o1); }
                *(float2*)(orow + col) = make_float2(o0, o1);
            }
        }
    }
}

// inner compute for one 16-k tile (LDS.128 fragments).
// RAW-spaced: per mt, issue aa0 across all nt, then aa1 across all nt —
// same-accumulator reuse distance 4 (per-acc op order unchanged -> bit-identical).
__device__ __forceinline__ void tile_mma(
    const float* __restrict__ smem, int Ab, int Astride, int Akb,
    int Wb, int wm, int wn, int g, int tq, float acc[4][4][4])
{
    float4 bf4[4];
#pragma unroll
    for (int nt = 0; nt < 4; ++nt)
        bf4[nt] = *(const float4*)&smem[Wb + (wn + nt * 8 + g) * 16 + tq];
#pragma unroll
    for (int mt = 0; mt < 4; ++mt) {
        const int r = wm + mt * 16 + g;
        const float4 a0 = *(const float4*)&smem[Ab + r * Astride + Akb + tq];
        const float4 a1 = *(const float4*)&smem[Ab + (r + 8) * Astride + Akb + tq];
        const unsigned aa0[4] = {fau(a0.x), fau(a1.x), fau(a0.y), fau(a1.y)};
        const unsigned aa1[4] = {fau(a0.z), fau(a1.z), fau(a0.w), fau(a1.w)};
#pragma unroll
        for (int nt = 0; nt < 4; ++nt) {
            const unsigned b0[2] = {fau(bf4[nt].x), fau(bf4[nt].y)};
            mma8(acc[mt][nt], aa0, b0);
        }
#pragma unroll
        for (int nt = 0; nt < 4; ++nt) {
            const unsigned b1[2] = {fau(bf4[nt].z), fau(bf4[nt].w)};
            mma8(acc[mt][nt], aa1, b1);
        }
    }
}

// ---------------------------------------------------------------------------
// Generic GEMM core: 4-stage cp.async, swizzled 16-word rows, LDS.128 frags.
// CVTST=1: A staged via LDG+cvt+STS (reg prefetch); CVTST=0: A via cp.async.
// ---------------------------------------------------------------------------
template <int EPI, int RND, int CVTST>
__device__ __forceinline__ void mma_gemm(
    const float* __restrict__ A, int lda,
    const float* __restrict__ W, int K,
    const float* __restrict__ bias,
    const float* __restrict__ lng, const float* __restrict__ lnb,
    const float* __restrict__ addv,
    const float* __restrict__ resid, int rstride,
    float* __restrict__ out, int ostride,
    int m0, int M)
{
    extern __shared__ float smem[];
    __syncthreads();

    const int tid   = threadIdx.x;
    const int ldRow = tid >> 1;
    const int ldCol = (tid & 1) * 8;
    const int c0    = ldCol >> 2;
    const int rsw   = ldRow & 3;

    const float* Aptr = A + (long)min(m0 + ldRow, M - 1) * lda + ldCol;
    const float* Wptr = W + (long)ldRow * K + ldCol;

    const unsigned sb  = (unsigned)__cvta_generic_to_shared(smem);
    const unsigned aq0 = sb + (ldRow * 16 + ((c0    ) ^ rsw) * 4) * 4;
    const unsigned aq1 = sb + (ldRow * 16 + ((c0 + 1) ^ rsw) * 4) * 4;
    const unsigned wq0 = aq0 + NST * STW * 4;
    const unsigned wq1 = aq1 + NST * STW * 4;
    const int d0off = ldRow * 16 + ((c0    ) ^ rsw) * 4;
    const int d1off = ldRow * 16 + ((c0 + 1) ^ rsw) * 4;

    const int wid = tid >> 5, lane = tid & 31;
    const int wm = (wid & 1) * 64, wn = (wid >> 1) * 32;
    const int g = lane >> 2, t4 = lane & 3;
    const int tq = (t4 ^ (g & 3)) * 4;

    float acc[4][4][4] = {};
    const int ntiles = K >> 4;

    float4 ra, rb;
    if (CVTST) {
        const float4 t0a = *(const float4*)(Aptr);
        const float4 t0b = *(const float4*)(Aptr + 4);
        *(float4*)&smem[d0off] = make_float4(tfr(t0a.x), tfr(t0a.y), tfr(t0a.z), tfr(t0a.w));
        *(float4*)&smem[d1off] = make_float4(tfr(t0b.x), tfr(t0b.y), tfr(t0b.z), tfr(t0b.w));
        ra = *(const float4*)(Aptr + 16);
        rb = *(const float4*)(Aptr + 20);
#pragma unroll
        for (int p = 0; p < 3; ++p) {
            cp16(wq0 + p * 8192, Wptr + p * 16);
            cp16(wq1 + p * 8192, Wptr + p * 16 + 4);
            cp_commit();
        }
    } else {
#pragma unroll
        for (int p = 0; p < 3; ++p) {
            const int k0 = p << 4;
            cp16(aq0 + p * 8192, Aptr + k0);
            cp16(aq1 + p * 8192, Aptr + k0 + 4);
            cp16(wq0 + p * 8192, Wptr + k0);
            cp16(wq1 + p * 8192, Wptr + k0 + 4);
            cp_commit();
        }
    }

    int cur = 0;
    for (int t = 0; t < ntiles; ++t) {
        if (t + 3 <= ntiles)      cp_wait<2>();
        else if (t + 2 <= ntiles) cp_wait<1>();
        else                      cp_wait<0>();
        __syncthreads();

        if (t + 3 < ntiles) {
            const int buf = (cur + 3) & 3;
            const int k0 = (t + 3) << 4;
            if (!CVTST) {
                cp16(aq0 + buf * 8192, Aptr + k0);
                cp16(aq1 + buf * 8192, Aptr + k0 + 4);
            }
            cp16(wq0 + buf * 8192, Wptr + k0);
            cp16(wq1 + buf * 8192, Wptr + k0 + 4);
            cp_commit();
        }

        if (CVTST) {
            if (t + 1 < ntiles) {
                const int nb = (cur + 1) & 3;
                *(float4*)&smem[nb * STW + d0off] =
                    make_float4(tfr(ra.x), tfr(ra.y), tfr(ra.z), tfr(ra.w));
                *(float4*)&smem[nb * STW + d1off] =
                    make_float4(tfr(rb.x), tfr(rb.y), tfr(rb.z), tfr(rb.w));
            }
            if (t + 2 < ntiles) {
                const int k0 = (t + 2) << 4;
                ra = *(const float4*)(Aptr + k0);
                rb = *(const float4*)(Aptr + k0 + 4);
            }
        }

        tile_mma(smem, cur * STW, 16, 0, NST * STW + cur * STW, wm, wn, g, tq, acc);
        cur = (cur + 1) & 3;
    }

    epi_store<EPI, RND>(acc, bias, lng, lnb, addv, resid, rstride, out, ostride, m0, M);
}

// ---------------------------------------------------------------------------
// Resident-A runner (K=128, NJ jobs sharing A). A staged once (cp.async, raw
// tf32, swizzled), W 4-stage pipeline continuous across jobs.
// ---------------------------------------------------------------------------
template <int NJ, int EPI, int RND>
__device__ __forceinline__ void resA_run(
    const float* __restrict__ A, int lda, int m0, int M,
    const float* const* Wj, const float* const* bj,
    float* const* oj, const int* osj)
{
    extern __shared__ float smem[];
    const int tid = threadIdx.x;
    const int ldRow = tid >> 1, hh = tid & 1;
    const int rsw = ldRow & 3;
    const unsigned sb = (unsigned)__cvta_generic_to_shared(smem);

    // stage A (128x128 raw tf32) into swizzled Af[128][AFP2]
    {
        const float* Ap = A + (long)min(m0 + ldRow, M - 1) * lda + hh * 64;
#pragma unroll
        for (int j = 0; j < 16; ++j) {
            const int b  = hh * 4 + (j >> 2);
            const int qn = (j & 3) ^ rsw;
            cp16(sb + (ldRow * AFP2 + b * 16 + qn * 4) * 4, Ap + 4 * j);
        }
    }
    const int c0 = hh * 2;
    const unsigned wq0 = sb + (QW2 + ldRow * 16 + ((c0    ) ^ rsw) * 4) * 4;
    const unsigned wq1 = sb + (QW2 + ldRow * 16 + ((c0 + 1) ^ rsw) * 4) * 4;
    {
        const float* wp = Wj[0] + (long)ldRow * 128 + hh * 8;
        cp16(wq0, wp); cp16(wq1, wp + 4); cp_commit();      // group 0: A + W tile0
        cp16(wq0 + 8192, wp + 16); cp16(wq1 + 8192, wp + 20); cp_commit();
        cp16(wq0 + 16384, wp + 32); cp16(wq1 + 16384, wp + 36); cp_commit();
    }

    const int wid = tid >> 5, lane = tid & 31;
    const int wm = (wid & 1) * 64, wn = (wid >> 1) * 32;
    const int g = lane >> 2, t4 = lane & 3;
    const int tq = (t4 ^ (g & 3)) * 4;
    const int NT = NJ * 8;

    float acc[4][4][4] = {};
    int cur = 0;

#pragma unroll 1
    for (int j = 0; j < NJ; ++j) {
#pragma unroll 1
        for (int t = 0; t < 8; ++t) {
            const int jt = j * 8 + t;
            if (jt + 3 <= NT)      cp_wait<2>();
            else if (jt + 2 <= NT) cp_wait<1>();
            else                   cp_wait<0>();
            __syncthreads();
            if (jt + 3 < NT) {
                const int pj = (jt + 3) >> 3, pt = (jt + 3) & 7;
                const float* wp = Wj[pj] + (long)ldRow * 128 + pt * 16 + hh * 8;
                const int buf = (cur + 3) & 3;
                cp16(wq0 + buf * 8192, wp);
                cp16(wq1 + buf * 8192, wp + 4);
                cp_commit();
            }
            tile_mma(smem, 0, AFP2, t * 16, QW2 + cur * STW, wm, wn, g, tq, acc);
            cur = (cur + 1) & 3;
        }
        epi_store<EPI, RND>(acc, bj[j], nullptr, nullptr, nullptr, nullptr, 0,
                            oj[j], osj[j], m0, M);
#pragma unroll
        for (int a = 0; a < 4; ++a)
#pragma unroll
            for (int b = 0; b < 4; ++b)
#pragma unroll
                for (int c = 0; c < 4; ++c) acc[a][b][c] = 0.f;
    }
}

// ---------------- kernels ----------------

// merged spatial + gf: y=0 -> spatial (K=1280), y=1,2 -> gf stream y-1
__global__ __launch_bounds__(256, 2) void k_g_proj(
    const float* __restrict__ Xs, const float* __restrict__ Xg,
    const float* __restrict__ Xf,
    const float* __restrict__ pb, const float* __restrict__ lng,
    const float* __restrict__ lnb, const float* __restrict__ mod, int M)
{
    const int y = blockIdx.y;
    if (y == 0) {
        mma_gemm<2, 1, 1>(Xs, 1280, g_wtf + WOFF_SPATIAL, 1280, pb, lng, lnb, mod,
                          nullptr, 0, g_P, 384, blockIdx.x * 128, M);
    } else {
        const int s = y - 1, n = y;
        mma_gemm<2, 1, 1>(s ? Xf : Xg, 128, g_wtf + WOFF_GF + s * 128 * 128, 128,
                          pb + n * 128, lng + n * 128, lnb + n * 128, mod + n * 128,
                          nullptr, 0, g_P + n * 128, 384, blockIdx.x * 128, M);
    }
}

__global__ __launch_bounds__(256, 2) void k_g_qkv(
    const float* __restrict__ Bi, int M)
{
    const int s  = blockIdx.y;
    const int m0 = blockIdx.x * 128;
    float* bufs[3] = {g_q, g_k, g_v};
    const float* Wj[5]; const float* bj[5]; float* oj[5]; int osj[5];
#pragma unroll
    for (int j = 0; j < 5; ++j) {
        Wj[j]  = g_wtf + WOFF_INW + qkv_jobs[s][j][0];
        bj[j]  = Bi + qkv_jobs[s][j][1];
        const int bid = qkv_jobs[s][j][2];
        oj[j]  = bufs[bid] + qkv_jobs[s][j][3];
        osj[j] = (bid == 0) ? 384 : 768;
    }
    resA_run<5, 0, 0>(g_P + s * 128, 384, m0, M, Wj, bj, oj, osj);
}

__global__ __launch_bounds__(256, 2) void k_g_outproj(
    const float* __restrict__ bo,
    const float* __restrict__ ag, const float* __restrict__ ab, int M)
{
    const int n = blockIdx.y;
    mma_gemm<3, 1, 0>(g_o + n * 128, 384, g_wtf + WOFF_OUTW + n * 128 * 128, 128,
                      bo + n * 128, ag + n * 128, ab + n * 128, nullptr,
                      g_P + n * 128, 384, g_x1 + n * 128, 384, blockIdx.x * 128, M);
}

__global__ __launch_bounds__(256, 2) void k_g_ffn1(
    const float* __restrict__ B1, int M)
{
    const int n  = blockIdx.y;
    const int m0 = blockIdx.x * 128;
    const float* Wj[2] = { g_wtf + WOFF_FFN1 + n * 32768,
                           g_wtf + WOFF_FFN1 + n * 32768 + 16384 };
    const float* bj[2] = { B1 + n * 256, B1 + n * 256 + 128 };
    float* oj[2] = { g_h + n * 256, g_h + n * 256 + 128 };
    int osj[2] = { 768, 768 };
    resA_run<2, 1, 1>(g_x1 + n * 128, 384, m0, M, Wj, bj, oj, osj);
}

__global__ __launch_bounds__(256, 2) void k_g_ffn2(
    const float* __restrict__ B2,
    const float* __restrict__ fg, const float* __restrict__ fb, int M)
{
    const int n = blockIdx.y;
    mma_gemm<3, 0, 0>(g_h + n * 256, 768, g_wtf + WOFF_FFN2 + n * 128 * 256, 256,
                      B2 + n * 128, fg + n * 128, fb + n * 128, nullptr,
                      g_x1 + n * 128, 384, g_x2 + n * 128, 384, blockIdx.x * 128, M);
}

// ---------------- weight tf32 pre-convert (single launch) ----------------
__global__ __launch_bounds__(256) void k_cvt_all(
    const float* __restrict__ s0, const float* __restrict__ s1,
    const float* __restrict__ s2, const float* __restrict__ s3,
    const float* __restrict__ s4, const float* __restrict__ s5)
{
    const int i = blockIdx.x * 256 + threadIdx.x;
    if (i >= 147456) return;
    const float* src; int base;
    if      (i <  40960) { src = s0; base = 0;      }
    else if (i <  49152) { src = s1; base = 40960;  }
    else if (i <  86016) { src = s2; base = 49152;  }
    else if (i <  98304) { src = s3; base = 86016;  }
    else if (i < 122880) { src = s4; base = 98304;  }
    else                 { src = s5; base = 122880; }
    const float4 v = ((const float4*)src)[i - base];
    float4 o;
    o.x = tfr(v.x); o.y = tfr(v.y); o.z = tfr(v.z); o.w = tfr(v.w);
    ((float4*)g_wtf)[i] = o;
}

// ---------------- Attention + gate ----------------

__global__ __launch_bounds__(256) void k_attn(int M)
{
    const int rid = blockIdx.x * 8 + (threadIdx.x >> 5);
    if (rid >= M * 3) return;
    const int lane = threadIdx.x & 31;
    const int d4 = lane * 4;
    const long qb = (long)rid * 128;
    const long kb = (long)rid * 256;

    const float4 q4  = *(const float4*)(g_q + qb + d4);
    const float4 k04 = *(const float4*)(g_k + kb + d4);
    const float4 k14 = *(const float4*)(g_k + kb + 128 + d4);
    const float4 v04 = *(const float4*)(g_v + kb + d4);
    const float4 v14 = *(const float4*)(g_v + kb + 128 + d4);

    float s0 = q4.x * k04.x + q4.y * k04.y + q4.z * k04.z + q4.w * k04.w;
    float s1 = q4.x * k14.x + q4.y * k14.y + q4.z * k14.z + q4.w * k14.w;
#pragma unroll
    for (int o = 4; o; o >>= 1) {
        s0 += __shfl_xor_sync(0xffffffffu, s0, o);
        s1 += __shfl_xor_sync(0xffffffffu, s1, o);
    }
    const float scale = 0.17677669529663687f;
    s0 *= scale; s1 *= scale;
    const float mx = fmaxf(s0, s1);
    const float e0 = expf(s0 - mx), e1 = expf(s1 - mx);
    const float inv = 1.0f / (e0 + e1);
    const float w0 = e0 * inv, w1 = e1 * inv;

    float4 o4;   // tf32-rounded: feeds outproj GEMM as A
    o4.x = tfr(w0 * v04.x + w1 * v14.x);
    o4.y = tfr(w0 * v04.y + w1 * v14.y);
    o4.z = tfr(w0 * v04.z + w1 * v14.z);
    o4.w = tfr(w0 * v04.w + w1 * v14.w);
    *(float4*)(g_o + qb + d4) = o4;
}

__global__ __launch_bounds__(256) void k_gate(
    const float* __restrict__ gw, const float* __restrict__ gb,
    float* __restrict__ out, int M)
{
    const int b = blockIdx.x * 8 + (threadIdx.x >> 5);
    if (b >= M) return;
    const int lane = threadIdx.x & 31;
    const float* xr = g_x2 + (long)b * 384;
    float l0 = 0.f, l1 = 0.f, l2 = 0.f;
#pragma unroll
    for (int j = 0; j < 12; ++j) {
        const int idx = lane + 32 * j;
        const float x = xr[idx];
        l0 += x * gw[idx];
        l1 += x * gw[384 + idx];
        l2 += x * gw[768 + idx];
    }
#pragma unroll
    for (int o = 16; o; o >>= 1) {
        l0 += __shfl_xor_sync(0xffffffffu, l0, o);
        l1 += __shfl_xor_sync(0xffffffffu, l1, o);
        l2 += __shfl_xor_sync(0xffffffffu, l2, o);
    }
    l0 += gb[0]; l1 += gb[1]; l2 += gb[2];
    const float mx = fmaxf(l0, fmaxf(l1, l2));
    const float e0 = expf(l0 - mx), e1 = expf(l1 - mx), e2 = expf(l2 - mx);
    const float inv = 1.0f / (e0 + e1 + e2);
    const float w0 = e0 * inv, w1 = e1 * inv, w2 = e2 * inv;
#pragma unroll
    for (int j = 0; j < 4; ++j) {
        const int d = lane + 32 * j;
        out[(long)b * 128 + d] = w0 * xr[d] + w1 * xr[128 + d] + w2 * xr[256 + d];
    }
}

// ---------------------------------------------------------------------------

extern "C" void kernel_launch(void* const* d_in, const int* in_sizes, int n_in,
                              void* d_out, int out_size)
{
    const float* x_spatial   = (const float*)d_in[0];
    const float* x_gradient  = (const float*)d_in[1];
    const float* x_frequency = (const float*)d_in[2];
    const float* w_spatial   = (const float*)d_in[3];
    const float* w_gf        = (const float*)d_in[4];
    const float* proj_b      = (const float*)d_in[5];
    const float* proj_ln_g   = (const float*)d_in[6];
    const float* proj_ln_b   = (const float*)d_in[7];
    const float* mod_emb     = (const float*)d_in[8];
    const float* in_w        = (const float*)d_in[9];
    const float* in_b        = (const float*)d_in[10];
    const float* out_w       = (const float*)d_in[11];
    const float* out_b       = (const float*)d_in[12];
    const float* attn_g      = (const float*)d_in[13];
    const float* attn_b      = (const float*)d_in[14];
    const float* w1          = (const float*)d_in[15];
    const float* b1          = (const float*)d_in[16];
    const float* w2          = (const float*)d_in[17];
    const float* b2          = (const float*)d_in[18];
    const float* ffn_g       = (const float*)d_in[19];
    const float* ffn_b       = (const float*)d_in[20];
    const float* gate_w      = (const float*)d_in[21];
    const float* gate_b      = (const float*)d_in[22];
    float* out = (float*)d_out;

    static int smem_set = 0;
    if (!smem_set) {
        cudaFuncSetAttribute(k_g_proj,    cudaFuncAttributeMaxDynamicSharedMemorySize, GSMEM);
        cudaFuncSetAttribute(k_g_qkv,     cudaFuncAttributeMaxDynamicSharedMemorySize, QSMEM);
        cudaFuncSetAttribute(k_g_outproj, cudaFuncAttributeMaxDynamicSharedMemorySize, GSMEM);
        cudaFuncSetAttribute(k_g_ffn1,    cudaFuncAttributeMaxDynamicSharedMemorySize, QSMEM);
        cudaFuncSetAttribute(k_g_ffn2,    cudaFuncAttributeMaxDynamicSharedMemorySize, GSMEM);
        smem_set = 1;
    }

    int B = in_sizes[0] / 1280;
    if (B > MAXB) B = MAXB;
    const int gm = (B + 127) / 128;
    const int R  = B * 3;

    k_cvt_all<<<(147456 + 255) / 256, 256>>>(w_spatial, w_gf, in_w, out_w, w1, w2);

    k_g_proj<<<dim3(gm, 3), 256, GSMEM>>>(x_spatial, x_gradient, x_frequency,
                                          proj_b, proj_ln_g, proj_ln_b, mod_emb, B);
    k_g_qkv<<<dim3(gm, 3), 256, QSMEM>>>(in_b, B);
    k_attn<<<(R + 7) / 8, 256>>>(B);
    k_g_outproj<<<dim3(gm, 3), 256, GSMEM>>>(out_b, attn_g, attn_b, B);
    k_g_ffn1<<<dim3(gm, 3), 256, QSMEM>>>(b1, B);
    k_g_ffn2<<<dim3(gm, 3), 256, GSMEM>>>(b2, ffn_g, ffn_b, B);
    k_gate<<<(B + 7) / 8, 256>>>(gate_w, gate_b, out, B);
}

// round 16
// speedup vs baseline: 1.2249x; 1.0090x over previous
#include <cuda_runtime.h>
#include <math.h>

// ---------------------------------------------------------------------------
// CMAF fused block, round 16 = round 15 +
//   resident-A path (qkv, ffn1) converted to BK=32 stages, 2 W buffers:
//   one cp_wait+__syncthreads per 32-k stage (barriers halved), 2 tile_mma
//   per sync window, W load for stage t+1 issued right after the sync.
// ---------------------------------------------------------------------------

#define MAXB 65536
#define NST 4
#define STW 2048                         // words per 16-k chunk (128 rows x 16)
#define GSMEM (2 * NST * STW * 4)        // 65536 B (generic path)

#define AFP2 144                         // resident-A row stride (=16 mod 32)
#define QW2 (128 * AFP2)                 // words
#define WSTG 4096                        // words per 32-k W stage (2 chunks)
#define QSMEM ((QW2 + 2 * WSTG) * 4)     // 106496 B (resident path)

__device__ __align__(16) float g_P [MAXB * 3 * 128];
__device__ __align__(16) float g_q [MAXB * 3 * 128];
__device__ __align__(16) float g_k [MAXB * 6 * 128];
__device__ __align__(16) float g_v [MAXB * 6 * 128];
__device__ __align__(16) float g_o [MAXB * 3 * 128];
__device__ __align__(16) float g_x1[MAXB * 3 * 128];
__device__ __align__(16) float g_h [MAXB * 3 * 256];
__device__ __align__(16) float g_x2[MAXB * 3 * 128];

// tf32-preconverted weights (contiguous: spatial|gf|inw|outw|ffn1|ffn2)
#define WOFF_SPATIAL 0
#define WOFF_GF      163840
#define WOFF_INW     196608
#define WOFF_OUTW    344064
#define WOFF_FFN1    393216
#define WOFF_FFN2    491520
__device__ __align__(16) float g_wtf[589824];

// QKV jobs per source stream s: {w_off (within in_w), b_off, buf_id, out_off}
__constant__ int qkv_jobs[3][5][4] = {
    { {     0,    0, 0,   0}, { 65536,  512, 1, 256}, { 81920,  640, 2, 256},
      {114688,  896, 1, 512}, {131072, 1024, 2, 512} },
    { { 49152,  384, 0, 128}, { 16384,  128, 1,   0}, { 32768,  256, 2,   0},
      {114688,  896, 1, 640}, {131072, 1024, 2, 640} },
    { { 98304,  768, 0, 256}, { 16384,  128, 1, 128}, { 32768,  256, 2, 128},
      { 65536,  512, 1, 384}, { 81920,  640, 2, 384} },
};

__device__ __forceinline__ unsigned f2tf(float f) {
    unsigned u;
    asm("cvt.rna.tf32.f32 %0, %1;" : "=r"(u) : "f"(f));
    return u;
}
__device__ __forceinline__ float tfr(float f) {
    return __uint_as_float(f2tf(f));
}
__device__ __forceinline__ unsigned fau(float f) { return __float_as_uint(f); }

__device__ __forceinline__ void mma8(float c[4], const unsigned a[4], const unsigned b[2]) {
    asm volatile(
        "mma.sync.aligned.m16n8k8.row.col.f32.tf32.tf32.f32 "
        "{%0,%1,%2,%3}, {%4,%5,%6,%7}, {%8,%9}, {%0,%1,%2,%3};\n"
        : "+f"(c[0]), "+f"(c[1]), "+f"(c[2]), "+f"(c[3])
        : "r"(a[0]), "r"(a[1]), "r"(a[2]), "r"(a[3]), "r"(b[0]), "r"(b[1]));
}

__device__ __forceinline__ void cp16(unsigned smem_dst, const void* gsrc) {
    asm volatile("cp.async.cg.shared.global [%0], [%1], 16;\n"
                 :: "r"(smem_dst), "l"(gsrc));
}
__device__ __forceinline__ void cp_commit() {
    asm volatile("cp.async.commit_group;\n");
}
template <int N>
__device__ __forceinline__ void cp_wait() {
    asm volatile("cp.async.wait_group %0;\n" :: "n"(N));
}

// ---------------------------------------------------------------------------
// Epilogue. EPI: 0=bias, 1=bias+gelu, 2=bias+LN+addv, 3=bias+resid+LN
// RND: store tf32-rounded.
// ---------------------------------------------------------------------------
template <int EPI, int RND>
__device__ __forceinline__ void epi_store(
    float acc[4][4][4],
    const float* __restrict__ bias,
    const float* __restrict__ lng, const float* __restrict__ lnb,
    const float* __restrict__ addv,
    const float* __restrict__ resid, int rstride,
    float* __restrict__ out, int ostride, int m0, int M)
{
    __shared__ float2 pbuf[128][4];
    const int tid = threadIdx.x, wid = tid >> 5, lane = tid & 31;
    const int wm = (wid & 1) * 64, wn = (wid >> 1) * 32, wq = wid >> 1;
    const int g = lane >> 2, t4 = lane & 3;

    float b2[4][2];
#pragma unroll
    for (int nt = 0; nt < 4; ++nt) {
        const int col = wn + nt * 8 + t4 * 2;
        b2[nt][0] = bias[col]; b2[nt][1] = bias[col + 1];
    }

    if (EPI <= 1) {
#pragma unroll
        for (int mt = 0; mt < 4; ++mt)
#pragma unroll
        for (int hf = 0; hf < 2; ++hf) {
            const int r = m0 + wm + mt * 16 + hf * 8 + g;
            if (r < M) {
                float* orow = out + (long)r * ostride;
#pragma unroll
                for (int nt = 0; nt < 4; ++nt) {
                    const int col = wn + nt * 8 + t4 * 2;
                    float c0 = acc[mt][nt][hf * 2 + 0] + b2[nt][0];
                    float c1 = acc[mt][nt][hf * 2 + 1] + b2[nt][1];
                    if (EPI == 1) {
                        c0 = c0 * 0.5f * (1.0f + erff(c0 * 0.70710678118654752f));
                        c1 = c1 * 0.5f * (1.0f + erff(c1 * 0.70710678118654752f));
                    }
                    if (RND) { c0 = tfr(c0); c1 = tfr(c1); }
                    *(float2*)(orow + col) = make_float2(c0, c1);
                }
            }
        }
        return;
    }

    // LN path
#pragma unroll
    for (int mt = 0; mt < 4; ++mt)
#pragma unroll
    for (int hf = 0; hf < 2; ++hf) {
        const int lr = wm + mt * 16 + hf * 8 + g;
        const int r  = m0 + lr;
        float s = 0.f, s2 = 0.f;
        const float* rrow = (EPI == 3) ? resid + (long)min(r, M - 1) * rstride : (const float*)0;
#pragma unroll
        for (int nt = 0; nt < 4; ++nt) {
            const int col = wn + nt * 8 + t4 * 2;
            float c0 = acc[mt][nt][hf * 2 + 0] + b2[nt][0];
            float c1 = acc[mt][nt][hf * 2 + 1] + b2[nt][1];
            if (EPI == 3) {
                const float2 rv = *(const float2*)(rrow + col);
                c0 += rv.x; c1 += rv.y;
            }
            acc[mt][nt][hf * 2 + 0] = c0; acc[mt][nt][hf * 2 + 1] = c1;
            s += c0 + c1; s2 += c0 * c0 + c1 * c1;
        }
        s  += __shfl_xor_sync(0xffffffffu, s, 1);
        s  += __shfl_xor_sync(0xffffffffu, s, 2);
        s2 += __shfl_xor_sync(0xffffffffu, s2, 1);
        s2 += __shfl_xor_sync(0xffffffffu, s2, 2);
        if (t4 == 0) pbuf[lr][wq] = make_float2(s, s2);
    }
    __syncthreads();
#pragma unroll
    for (int mt = 0; mt < 4; ++mt)
#pragma unroll
    for (int hf = 0; hf < 2; ++hf) {
        const int lr = wm + mt * 16 + hf * 8 + g;
        const int r  = m0 + lr;
        const float2 p0 = pbuf[lr][0], p1 = pbuf[lr][1], p2 = pbuf[lr][2], p3 = pbuf[lr][3];
        const float s    = p0.x + p1.x + p2.x + p3.x;
        const float s2   = p0.y + p1.y + p2.y + p3.y;
        const float mean = s * 0.0078125f;
        const float var  = s2 * 0.0078125f - mean * mean;
        const float rs   = rsqrtf(var + 1e-5f);
        if (r < M) {
            float* orow = out + (long)r * ostride;
#pragma unroll
            for (int nt = 0; nt < 4; ++nt) {
                const int col = wn + nt * 8 + t4 * 2;
                float o0 = (acc[mt][nt][hf * 2 + 0] - mean) * rs * lng[col]     + lnb[col];
                float o1 = (acc[mt][nt][hf * 2 + 1] - mean) * rs * lng[col + 1] + lnb[col + 1];
                if (EPI == 2) { o0 += addv[col]; o1 += addv[col + 1]; }
                if (RND) { o0 = tfr(o0); o1 = tfr(o1); }
                *(float2*)(orow + col) = make_float2(o0, o1);
            }
        }
    }
}

// inner compute for one 16-k tile (LDS.128 fragments, RAW-spaced issue)
__device__ __forceinline__ void tile_mma(
    const float* __restrict__ smem, int Ab, int Astride, int Akb,
    int Wb, int wm, int wn, int g, int tq, float acc[4][4][4])
{
    float4 bf4[4];
#pragma unroll
    for (int nt = 0; nt < 4; ++nt)
        bf4[nt] = *(const float4*)&smem[Wb + (wn + nt * 8 + g) * 16 + tq];
#pragma unroll
    for (int mt = 0; mt < 4; ++mt) {
        const int r = wm + mt * 16 + g;
        const float4 a0 = *(const float4*)&smem[Ab + r * Astride + Akb + tq];
        const float4 a1 = *(const float4*)&smem[Ab + (r + 8) * Astride + Akb + tq];
        const unsigned aa0[4] = {fau(a0.x), fau(a1.x), fau(a0.y), fau(a1.y)};
        const unsigned aa1[4] = {fau(a0.z), fau(a1.z), fau(a0.w), fau(a1.w)};
#pragma unroll
        for (int nt = 0; nt < 4; ++nt) {
            const unsigned b0[2] = {fau(bf4[nt].x), fau(bf4[nt].y)};
            mma8(acc[mt][nt], aa0, b0);
        }
#pragma unroll
        for (int nt = 0; nt < 4; ++nt) {
            const unsigned b1[2] = {fau(bf4[nt].z), fau(bf4[nt].w)};
            mma8(acc[mt][nt], aa1, b1);
        }
    }
}

// ---------------------------------------------------------------------------
// Generic GEMM core: 4-stage cp.async, swizzled 16-word rows, LDS.128 frags.
// CVTST=1: A staged via LDG+cvt+STS (reg prefetch); CVTST=0: A via cp.async.
// (unchanged from R15)
// ---------------------------------------------------------------------------
template <int EPI, int RND, int CVTST>
__device__ __forceinline__ void mma_gemm(
    const float* __restrict__ A, int lda,
    const float* __restrict__ W, int K,
    const float* __restrict__ bias,
    const float* __restrict__ lng, const float* __restrict__ lnb,
    const float* __restrict__ addv,
    const float* __restrict__ resid, int rstride,
    float* __restrict__ out, int ostride,
    int m0, int M)
{
    extern __shared__ float smem[];
    __syncthreads();

    const int tid   = threadIdx.x;
    const int ldRow = tid >> 1;
    const int ldCol = (tid & 1) * 8;
    const int c0    = ldCol >> 2;
    const int rsw   = ldRow & 3;

    const float* Aptr = A + (long)min(m0 + ldRow, M - 1) * lda + ldCol;
    const float* Wptr = W + (long)ldRow * K + ldCol;

    const unsigned sb  = (unsigned)__cvta_generic_to_shared(smem);
    const unsigned aq0 = sb + (ldRow * 16 + ((c0    ) ^ rsw) * 4) * 4;
    const unsigned aq1 = sb + (ldRow * 16 + ((c0 + 1) ^ rsw) * 4) * 4;
    const unsigned wq0 = aq0 + NST * STW * 4;
    const unsigned wq1 = aq1 + NST * STW * 4;
    const int d0off = ldRow * 16 + ((c0    ) ^ rsw) * 4;
    const int d1off = ldRow * 16 + ((c0 + 1) ^ rsw) * 4;

    const int wid = tid >> 5, lane = tid & 31;
    const int wm = (wid & 1) * 64, wn = (wid >> 1) * 32;
    const int g = lane >> 2, t4 = lane & 3;
    const int tq = (t4 ^ (g & 3)) * 4;

    float acc[4][4][4] = {};
    const int ntiles = K >> 4;

    float4 ra, rb;
    if (CVTST) {
        const float4 t0a = *(const float4*)(Aptr);
        const float4 t0b = *(const float4*)(Aptr + 4);
        *(float4*)&smem[d0off] = make_float4(tfr(t0a.x), tfr(t0a.y), tfr(t0a.z), tfr(t0a.w));
        *(float4*)&smem[d1off] = make_float4(tfr(t0b.x), tfr(t0b.y), tfr(t0b.z), tfr(t0b.w));
        ra = *(const float4*)(Aptr + 16);
        rb = *(const float4*)(Aptr + 20);
#pragma unroll
        for (int p = 0; p < 3; ++p) {
            cp16(wq0 + p * 8192, Wptr + p * 16);
            cp16(wq1 + p * 8192, Wptr + p * 16 + 4);
            cp_commit();
        }
    } else {
#pragma unroll
        for (int p = 0; p < 3; ++p) {
            const int k0 = p << 4;
            cp16(aq0 + p * 8192, Aptr + k0);
            cp16(aq1 + p * 8192, Aptr + k0 + 4);
            cp16(wq0 + p * 8192, Wptr + k0);
            cp16(wq1 + p * 8192, Wptr + k0 + 4);
            cp_commit();
        }
    }

    int cur = 0;
    for (int t = 0; t < ntiles; ++t) {
        if (t + 3 <= ntiles)      cp_wait<2>();
        else if (t + 2 <= ntiles) cp_wait<1>();
        else                      cp_wait<0>();
        __syncthreads();

        if (t + 3 < ntiles) {
            const int buf = (cur + 3) & 3;
            const int k0 = (t + 3) << 4;
            if (!CVTST) {
                cp16(aq0 + buf * 8192, Aptr + k0);
                cp16(aq1 + buf * 8192, Aptr + k0 + 4);
            }
            cp16(wq0 + buf * 8192, Wptr + k0);
            cp16(wq1 + buf * 8192, Wptr + k0 + 4);
            cp_commit();
        }

        if (CVTST) {
            if (t + 1 < ntiles) {
                const int nb = (cur + 1) & 3;
                *(float4*)&smem[nb * STW + d0off] =
                    make_float4(tfr(ra.x), tfr(ra.y), tfr(ra.z), tfr(ra.w));
                *(float4*)&smem[nb * STW + d1off] =
                    make_float4(tfr(rb.x), tfr(rb.y), tfr(rb.z), tfr(rb.w));
            }
            if (t + 2 < ntiles) {
                const int k0 = (t + 2) << 4;
                ra = *(const float4*)(Aptr + k0);
                rb = *(const float4*)(Aptr + k0 + 4);
            }
        }

        tile_mma(smem, cur * STW, 16, 0, NST * STW + cur * STW, wm, wn, g, tq, acc);
        cur = (cur + 1) & 3;
    }

    epi_store<EPI, RND>(acc, bias, lng, lnb, addv, resid, rstride, out, ostride, m0, M);
}

// ---------------------------------------------------------------------------
// Resident-A runner (K=128, NJ jobs sharing A), BK=32 stages, 2 W buffers.
// One cp_wait + __syncthreads per 32-k stage; W load for stage st+1 issued
// immediately after the sync (overlaps the 2-tile compute window).
// ---------------------------------------------------------------------------
template <int NJ, int EPI, int RND>
__device__ __forceinline__ void resA_run(
    const float* __restrict__ A, int lda, int m0, int M,
    const float* const* Wj, const float* const* bj,
    float* const* oj, const int* osj)
{
    extern __shared__ float smem[];
    const int tid = threadIdx.x;
    const int ldRow = tid >> 1, hh = tid & 1;
    const int rsw = ldRow & 3;
    const unsigned sb = (unsigned)__cvta_generic_to_shared(smem);

    // stage A (128x128 raw tf32) into swizzled Af[128][AFP2]
    {
        const float* Ap = A + (long)min(m0 + ldRow, M - 1) * lda + hh * 64;
#pragma unroll
        for (int j = 0; j < 16; ++j) {
            const int b  = hh * 4 + (j >> 2);
            const int qn = (j & 3) ^ rsw;
            cp16(sb + (ldRow * AFP2 + b * 16 + qn * 4) * 4, Ap + 4 * j);
        }
    }
    // per-thread W store offsets within a 16-k chunk (quad-XOR swizzled)
    const int c0 = hh * 2;
    const unsigned wo0 = (unsigned)((ldRow * 16 + ((c0    ) ^ rsw) * 4) * 4);
    const unsigned wo1 = (unsigned)((ldRow * 16 + ((c0 + 1) ^ rsw) * 4) * 4);
    const unsigned wbase = sb + QW2 * 4;

    // prologue: W stage 0 (job 0, k 0..31) shares the commit group with A
    {
        const float* wp = Wj[0] + (long)ldRow * 128 + hh * 8;
        cp16(wbase + wo0, wp);                    // chunk 0 (k 0..15)
        cp16(wbase + wo1, wp + 4);
        cp16(wbase + STW * 4 + wo0, wp + 16);     // chunk 1 (k 16..31)
        cp16(wbase + STW * 4 + wo1, wp + 20);
        cp_commit();
    }

    const int wid = tid >> 5, lane = tid & 31;
    const int wm = (wid & 1) * 64, wn = (wid >> 1) * 32;
    const int g = lane >> 2, t4 = lane & 3;
    const int tq = (t4 ^ (g & 3)) * 4;
    const int NTS = NJ * 4;   // 32-k stages total

    float acc[4][4][4] = {};

#pragma unroll 1
    for (int st = 0; st < NTS; ++st) {
        cp_wait<0>();          // stage st data (and A on st=0) complete
        __syncthreads();       // all warps done reading the other buffer

        if (st + 1 < NTS) {    // issue W stage st+1 into the other buffer
            const int pj = (st + 1) >> 2, ps = (st + 1) & 3;
            const float* wp = Wj[pj] + (long)ldRow * 128 + ps * 32 + hh * 8;
            const unsigned bs = wbase + ((st + 1) & 1) * WSTG * 4;
            cp16(bs + wo0, wp);
            cp16(bs + wo1, wp + 4);
            cp16(bs + STW * 4 + wo0, wp + 16);
            cp16(bs + STW * 4 + wo1, wp + 20);
            cp_commit();
        }

        const int akb = (st & 3) * 32;
        const int wb  = QW2 + (st & 1) * WSTG;
        tile_mma(smem, 0, AFP2, akb,      wb,       wm, wn, g, tq, acc);
        tile_mma(smem, 0, AFP2, akb + 16, wb + STW, wm, wn, g, tq, acc);

        if ((st & 3) == 3) {
            const int j = st >> 2;
            epi_store<EPI, RND>(acc, bj[j], nullptr, nullptr, nullptr, nullptr, 0,
                                oj[j], osj[j], m0, M);
#pragma unroll
            for (int a = 0; a < 4; ++a)
#pragma unroll
                for (int b = 0; b < 4; ++b)
#pragma unroll
                    for (int c = 0; c < 4; ++c) acc[a][b][c] = 0.f;
        }
    }
}

// ---------------- kernels ----------------

// merged spatial + gf: y=0 -> spatial (K=1280), y=1,2 -> gf stream y-1
__global__ __launch_bounds__(256, 2) void k_g_proj(
    const float* __restrict__ Xs, const float* __restrict__ Xg,
    const float* __restrict__ Xf,
    const float* __restrict__ pb, const float* __restrict__ lng,
    const float* __restrict__ lnb, const float* __restrict__ mod, int M)
{
    const int y = blockIdx.y;
    if (y == 0) {
        mma_gemm<2, 1, 1>(Xs, 1280, g_wtf + WOFF_SPATIAL, 1280, pb, lng, lnb, mod,
                          nullptr, 0, g_P, 384, blockIdx.x * 128, M);
    } else {
        const int s = y - 1, n = y;
        mma_gemm<2, 1, 1>(s ? Xf : Xg, 128, g_wtf + WOFF_GF + s * 128 * 128, 128,
                          pb + n * 128, lng + n * 128, lnb + n * 128, mod + n * 128,
                          nullptr, 0, g_P + n * 128, 384, blockIdx.x * 128, M);
    }
}

__global__ __launch_bounds__(256, 2) void k_g_qkv(
    const float* __restrict__ Bi, int M)
{
    const int s  = blockIdx.y;
    const int m0 = blockIdx.x * 128;
    float* bufs[3] = {g_q, g_k, g_v};
    const float* Wj[5]; const float* bj[5]; float* oj[5]; int osj[5];
#pragma unroll
    for (int j = 0; j < 5; ++j) {
        Wj[j]  = g_wtf + WOFF_INW + qkv_jobs[s][j][0];
        bj[j]  = Bi + qkv_jobs[s][j][1];
        const int bid = qkv_jobs[s][j][2];
        oj[j]  = bufs[bid] + qkv_jobs[s][j][3];
        osj[j] = (bid == 0) ? 384 : 768;
    }
    resA_run<5, 0, 0>(g_P + s * 128, 384, m0, M, Wj, bj, oj, osj);
}

__global__ __launch_bounds__(256, 2) void k_g_outproj(
    const float* __restrict__ bo,
    const float* __restrict__ ag, const float* __restrict__ ab, int M)
{
    const int n = blockIdx.y;
    mma_gemm<3, 1, 0>(g_o + n * 128, 384, g_wtf + WOFF_OUTW + n * 128 * 128, 128,
                      bo + n * 128, ag + n * 128, ab + n * 128, nullptr,
                      g_P + n * 128, 384, g_x1 + n * 128, 384, blockIdx.x * 128, M);
}

__global__ __launch_bounds__(256, 2) void k_g_ffn1(
    const float* __restrict__ B1, int M)
{
    const int n  = blockIdx.y;
    const int m0 = blockIdx.x * 128;
    const float* Wj[2] = { g_wtf + WOFF_FFN1 + n * 32768,
                           g_wtf + WOFF_FFN1 + n * 32768 + 16384 };
    const float* bj[2] = { B1 + n * 256, B1 + n * 256 + 128 };
    float* oj[2] = { g_h + n * 256, g_h + n * 256 + 128 };
    int osj[2] = { 768, 768 };
    resA_run<2, 1, 1>(g_x1 + n * 128, 384, m0, M, Wj, bj, oj, osj);
}

__global__ __launch_bounds__(256, 2) void k_g_ffn2(
    const float* __restrict__ B2,
    const float* __restrict__ fg, const float* __restrict__ fb, int M)
{
    const int n = blockIdx.y;
    mma_gemm<3, 0, 0>(g_h + n * 256, 768, g_wtf + WOFF_FFN2 + n * 128 * 256, 256,
                      B2 + n * 128, fg + n * 128, fb + n * 128, nullptr,
                      g_x1 + n * 128, 384, g_x2 + n * 128, 384, blockIdx.x * 128, M);
}

// ---------------- weight tf32 pre-convert (single launch) ----------------
__global__ __launch_bounds__(256) void k_cvt_all(
    const float* __restrict__ s0, const float* __restrict__ s1,
    const float* __restrict__ s2, const float* __restrict__ s3,
    const float* __restrict__ s4, const float* __restrict__ s5)
{
    const int i = blockIdx.x * 256 + threadIdx.x;
    if (i >= 147456) return;
    const float* src; int base;
    if      (i <  40960) { src = s0; base = 0;      }
    else if (i <  49152) { src = s1; base = 40960;  }
    else if (i <  86016) { src = s2; base = 49152;  }
    else if (i <  98304) { src = s3; base = 86016;  }
    else if (i < 122880) { src = s4; base = 98304;  }
    else                 { src = s5; base = 122880; }
    const float4 v = ((const float4*)src)[i - base];
    float4 o;
    o.x = tfr(v.x); o.y = tfr(v.y); o.z = tfr(v.z); o.w = tfr(v.w);
    ((float4*)g_wtf)[i] = o;
}

// ---------------- Attention + gate ----------------

__global__ __launch_bounds__(256) void k_attn(int M)
{
    const int rid = blockIdx.x * 8 + (threadIdx.x >> 5);
    if (rid >= M * 3) return;
    const int lane = threadIdx.x & 31;
    const int d4 = lane * 4;
    const long qb = (long)rid * 128;
    const long kb = (long)rid * 256;

    const float4 q4  = *(const float4*)(g_q + qb + d4);
    const float4 k04 = *(const float4*)(g_k + kb + d4);
    const float4 k14 = *(const float4*)(g_k + kb + 128 + d4);
    const float4 v04 = *(const float4*)(g_v + kb + d4);
    const float4 v14 = *(const float4*)(g_v + kb + 128 + d4);

    float s0 = q4.x * k04.x + q4.y * k04.y + q4.z * k04.z + q4.w * k04.w;
    float s1 = q4.x * k14.x + q4.y * k14.y + q4.z * k14.z + q4.w * k14.w;
#pragma unroll
    for (int o = 4; o; o >>= 1) {
        s0 += __shfl_xor_sync(0xffffffffu, s0, o);
        s1 += __shfl_xor_sync(0xffffffffu, s1, o);
    }
    const float scale = 0.17677669529663687f;
    s0 *= scale; s1 *= scale;
    const float mx = fmaxf(s0, s1);
    const float e0 = expf(s0 - mx), e1 = expf(s1 - mx);
    const float inv = 1.0f / (e0 + e1);
    const float w0 = e0 * inv, w1 = e1 * inv;

    float4 o4;   // tf32-rounded: feeds outproj GEMM as A
    o4.x = tfr(w0 * v04.x + w1 * v14.x);
    o4.y = tfr(w0 * v04.y + w1 * v14.y);
    o4.z = tfr(w0 * v04.z + w1 * v14.z);
    o4.w = tfr(w0 * v04.w + w1 * v14.w);
    *(float4*)(g_o + qb + d4) = o4;
}

__global__ __launch_bounds__(256) void k_gate(
    const float* __restrict__ gw, const float* __restrict__ gb,
    float* __restrict__ out, int M)
{
    const int b = blockIdx.x * 8 + (threadIdx.x >> 5);
    if (b >= M) return;
    const int lane = threadIdx.x & 31;
    const float* xr = g_x2 + (long)b * 384;
    float l0 = 0.f, l1 = 0.f, l2 = 0.f;
#pragma unroll
    for (int j = 0; j < 12; ++j) {
        const int idx = lane + 32 * j;
        const float x = xr[idx];
        l0 += x * gw[idx];
        l1 += x * gw[384 + idx];
        l2 += x * gw[768 + idx];
    }
#pragma unroll
    for (int o = 16; o; o >>= 1) {
        l0 += __shfl_xor_sync(0xffffffffu, l0, o);
        l1 += __shfl_xor_sync(0xffffffffu, l1, o);
        l2 += __shfl_xor_sync(0xffffffffu, l2, o);
    }
    l0 += gb[0]; l1 += gb[1]; l2 += gb[2];
    const float mx = fmaxf(l0, fmaxf(l1, l2));
    const float e0 = expf(l0 - mx), e1 = expf(l1 - mx), e2 = expf(l2 - mx);
    const float inv = 1.0f / (e0 + e1 + e2);
    const float w0 = e0 * inv, w1 = e1 * inv, w2 = e2 * inv;
#pragma unroll
    for (int j = 0; j < 4; ++j) {
        const int d = lane + 32 * j;
        out[(long)b * 128 + d] = w0 * xr[d] + w1 * xr[128 + d] + w2 * xr[256 + d];
    }
}

// ---------------------------------------------------------------------------

extern "C" void kernel_launch(void* const* d_in, const int* in_sizes, int n_in,
                              void* d_out, int out_size)
{
    const float* x_spatial   = (const float*)d_in[0];
    const float* x_gradient  = (const float*)d_in[1];
    const float* x_frequency = (const float*)d_in[2];
    const float* w_spatial   = (const float*)d_in[3];
    const float* w_gf        = (const float*)d_in[4];
    const float* proj_b      = (const float*)d_in[5];
    const float* proj_ln_g   = (const float*)d_in[6];
    const float* proj_ln_b   = (const float*)d_in[7];
    const float* mod_emb     = (const float*)d_in[8];
    const float* in_w        = (const float*)d_in[9];
    const float* in_b        = (const float*)d_in[10];
    const float* out_w       = (const float*)d_in[11];
    const float* out_b       = (const float*)d_in[12];
    const float* attn_g      = (const float*)d_in[13];
    const float* attn_b      = (const float*)d_in[14];
    const float* w1          = (const float*)d_in[15];
    const float* b1          = (const float*)d_in[16];
    const float* w2          = (const float*)d_in[17];
    const float* b2          = (const float*)d_in[18];
    const float* ffn_g       = (const float*)d_in[19];
    const float* ffn_b       = (const float*)d_in[20];
    const float* gate_w      = (const float*)d_in[21];
    const float* gate_b      = (const float*)d_in[22];
    float* out = (float*)d_out;

    static int smem_set = 0;
    if (!smem_set) {
        cudaFuncSetAttribute(k_g_proj,    cudaFuncAttributeMaxDynamicSharedMemorySize, GSMEM);
        cudaFuncSetAttribute(k_g_qkv,     cudaFuncAttributeMaxDynamicSharedMemorySize, QSMEM);
        cudaFuncSetAttribute(k_g_outproj, cudaFuncAttributeMaxDynamicSharedMemorySize, GSMEM);
        cudaFuncSetAttribute(k_g_ffn1,    cudaFuncAttributeMaxDynamicSharedMemorySize, QSMEM);
        cudaFuncSetAttribute(k_g_ffn2,    cudaFuncAttributeMaxDynamicSharedMemorySize, GSMEM);
        smem_set = 1;
    }

    int B = in_sizes[0] / 1280;
    if (B > MAXB) B = MAXB;
    const int gm = (B + 127) / 128;
    const int R  = B * 3;

    k_cvt_all<<<(147456 + 255) / 256, 256>>>(w_spatial, w_gf, in_w, out_w, w1, w2);

    k_g_proj<<<dim3(gm, 3), 256, GSMEM>>>(x_spatial, x_gradient, x_frequency,
                                          proj_b, proj_ln_g, proj_ln_b, mod_emb, B);
    k_g_qkv<<<dim3(gm, 3), 256, QSMEM>>>(in_b, B);
    k_attn<<<(R + 7) / 8, 256>>>(B);
    k_g_outproj<<<dim3(gm, 3), 256, GSMEM>>>(out_b, attn_g, attn_b, B);
    k_g_ffn1<<<dim3(gm, 3), 256, QSMEM>>>(b1, B);
    k_g_ffn2<<<dim3(gm, 3), 256, GSMEM>>>(b2, ffn_g, ffn_b, B);
    k_gate<<<(B + 7) / 8, 256>>>(gate_w, gate_b, out, B);
}